// round 7
// baseline (speedup 1.0000x reference)
#include <cuda_runtime.h>
#include <cuda_bf16.h>

#define BB 8
#define LL 4096
#define DD 1024
#define CC 128
#define WIN 64
#define NW (LL / WIN)          // 64 windows per batch

// Scan-published metadata
__device__ int4 g_chunk[BB][CC];      // {cnt, s, e, 0}
__device__ int  g_base[BB][NW];       // #boundaries in [0, w*WIN)
__device__ int  g_arrive[BB][CC];     // per-chunk arrival counters
__device__ int  g_ready[BB];          // per-batch metadata-ready flag (self-cleaning)
__device__ int  g_done[BB];           // per-batch window completion counters

// Window edge-piece partials (window-indexed: writable without scan results)
__device__ float4 g_head[BB][NW][DD / 4];
__device__ float4 g_tail[BB][NW][DD / 4];

// --- memory-model helpers ---
__device__ __forceinline__ int atomic_add_acq_rel(int* p, int v) {
    int old;
    asm volatile("atom.add.acq_rel.gpu.s32 %0, [%1], %2;"
                 : "=r"(old) : "l"(p), "r"(v) : "memory");
    return old;
}
__device__ __forceinline__ void st_release(int* p, int v) {
    asm volatile("st.release.gpu.s32 [%0], %1;" :: "l"(p), "r"(v) : "memory");
}
__device__ __forceinline__ int ld_acquire(const int* p) {
    int v;
    asm volatile("ld.acquire.gpu.s32 %0, [%1];" : "=r"(v) : "l"(p) : "memory");
    return v;
}

__device__ __forceinline__ void f4add(float4& a, const float4& v) {
    a.x += v.x; a.y += v.y; a.z += v.z; a.w += v.w;
}

// target = number of edge-touching pieces of chunk [s,e)
__device__ __forceinline__ int chunk_target(int s, int e) {
    int w0 = s >> 6, w1 = (e - 1) >> 6;
    if (w1 > w0) return w1 - w0 + 1;
    return (((s & 63) == 0) || ((e & 63) == 0)) ? 1 : 0;
}

// Deterministic finalize: fixed window order
__device__ __forceinline__ void finalize_chunk(int b, int c, int t,
                                               float* __restrict__ means) {
    const int4 mt = g_chunk[b][c];        // {cnt, s, e, 0}
    const int w0 = mt.y >> 6, w1 = (mt.z - 1) >> 6;
    float4 a = make_float4(0.f, 0.f, 0.f, 0.f);
    for (int ww = w0; ww <= w1; ww++) {
        float4 v = (((ww + 1) << 6) <= mt.z) ? g_tail[b][ww][t]
                                             : g_head[b][ww][t];
        f4add(a, v);
    }
    const float inv = 1.0f / (float)mt.x;
    a.x *= inv; a.y *= inv; a.z *= inv; a.w *= inv;
    reinterpret_cast<float4*>(means + ((size_t)b * CC + c) * DD)[t] = a;
}

// ---------------------------------------------------------------------------
// One fused kernel. bids 0..7 = scan blocks; bids 8..519 = window blocks.
// ---------------------------------------------------------------------------
__global__ void __launch_bounds__(256) chunk_win_kernel(
        const float* __restrict__ x,
        const float* __restrict__ boundaries,
        float* __restrict__ means,
        float* __restrict__ cnts_out,
        int write_cnts) {
    const int t    = threadIdx.x;
    const int lane = t & 31;
    const int wid  = t >> 5;

    if (blockIdx.x < BB) {
        // ====================== SCAN BLOCK ======================
        const int b = blockIdx.x;
        __shared__ int wsum[8], wexcl[8], pos[CC + 1], snb, elist[CC], s_ne;
        if (t == 0) s_ne = 0;

        const float* bp = boundaries + (size_t)b * LL;
        const int base16 = t * 16;
        unsigned flags = 0;
        {
            const float4* bp4 = reinterpret_cast<const float4*>(bp + base16);
#pragma unroll
            for (int q = 0; q < 4; q++) {
                float4 v = bp4[q];
                if (v.x > 0.5f) flags |= 1u << (q * 4 + 0);
                if (v.y > 0.5f) flags |= 1u << (q * 4 + 1);
                if (v.z > 0.5f) flags |= 1u << (q * 4 + 2);
                if (v.w > 0.5f) flags |= 1u << (q * 4 + 3);
            }
        }
        const int cnt = __popc(flags);

        int incl = cnt;
#pragma unroll
        for (int d = 1; d < 32; d <<= 1) {
            int v = __shfl_up_sync(0xFFFFFFFFu, incl, d);
            if (lane >= d) incl += v;
        }
        if (lane == 31) wsum[wid] = incl;
        __syncthreads();

        if (t < 8) {
            int v = wsum[t];
            int iv = v;
#pragma unroll
            for (int d = 1; d < 8; d <<= 1) {
                int u = __shfl_up_sync(0x000000FFu, iv, d);
                if (t >= d) iv += u;
            }
            wexcl[t] = iv - v;
            if (t == 7) snb = iv;
        }
        __syncthreads();

        const int excl = wexcl[wid] + (incl - cnt);   // boundaries before token base16
        if ((t & 3) == 0) g_base[b][t >> 2] = excl;   // 4 threads * 16 tok = 64 = WIN

        {
            int idx = excl;
            unsigned f = flags;
            while (f) {
                int i = __ffs(f) - 1;
                f &= f - 1;
                if (idx <= CC) pos[idx] = base16 + i;
                idx++;
            }
        }
        __syncthreads();

        const int nb = snb;
        const int valid = nb < CC ? nb : CC;

        if (t < CC) {
            int len = 0, s0 = 0, e0 = 0;
            if (t < valid) {
                s0 = pos[t];
                e0 = (t + 1 < nb) ? pos[t + 1] : LL;
                len = e0 - s0;
            }
            g_chunk[b][t]  = make_int4(len, s0, e0, 0);
            g_arrive[b][t] = 0;
            if (write_cnts) cnts_out[b * CC + t] = (float)len;
            if (len == 0) elist[atomicAdd(&s_ne, 1)] = t;
        }
        __syncthreads();

        // zero means of empty/invalid chunks (output poisoned 0xAA)
        const int ne = s_ne;
        const float4 z = make_float4(0.f, 0.f, 0.f, 0.f);
        for (int i = 0; i < ne; i++) {
            reinterpret_cast<float4*>(
                means + ((size_t)b * CC + elist[i]) * DD)[t] = z;
        }
        __syncthreads();

        if (t == 0) st_release(&g_ready[b], 1);
        return;
    }

    // ====================== WINDOW BLOCK ======================
    const int gw = blockIdx.x - BB;
    const int b  = gw >> 6;             // / NW
    const int w  = gw & (NW - 1);

    __shared__ int s_base, s_f0, s_f1;

    // boundary flags for this window: computed locally, no scan dependency
    const float* bpt = boundaries + (size_t)b * LL + w * WIN;
    const unsigned lo = __ballot_sync(0xFFFFFFFFu, bpt[lane]      > 0.5f);
    const unsigned hi = __ballot_sync(0xFFFFFFFFu, bpt[32 + lane] > 0.5f);
    const int f0 = lo & 1;

    const float4* __restrict__ xp =
        reinterpret_cast<const float4*>(x) +
        (size_t)(b * LL + w * WIN) * (DD / 4) + t;

    float4 acc = make_float4(0.f, 0.f, 0.f, 0.f);
    float4 h0  = acc, h1 = acc;         // held interior pieces m=1,2
    int ps = 0, M = 0, l1 = 0, l2 = 0;
    int base_v = -1;                    // lazily fetched on rare overflow path

    // software-pipelined stream of 64 tokens
    float4 b0 = xp[0 * 256], b1 = xp[1 * 256], b2 = xp[2 * 256], b3 = xp[3 * 256];

#pragma unroll
    for (int g = 0; g < 16; g++) {
        float4 n0, n1, n2, n3;
        if (g < 15) {
            const float4* q = xp + (size_t)(4 * g + 4) * 256;
            n0 = q[0 * 256]; n1 = q[1 * 256]; n2 = q[2 * 256]; n3 = q[3 * 256];
        }
#pragma unroll
        for (int u = 0; u < 4; u++) {
            const int j = 4 * g + u;
            float4 v = (u == 0) ? b0 : (u == 1) ? b1 : (u == 2) ? b2 : b3;
            if (j > 0) {
                const bool fb = (j < 32) ? ((lo >> j) & 1u) : ((hi >> (j - 32)) & 1u);
                if (fb) {   // boundary at token j: flush piece [ps, j)
                    const int len = j - ps;
                    if (M == 0) {
                        g_head[b][w][t] = acc;          // head piece
                    } else if (M == 1) {
                        h0 = acc; l1 = len;             // interior piece 1
                    } else if (M == 2) {
                        h1 = acc; l2 = len;             // interior piece 2
                    } else {
                        // rare: >2 interior pieces; need base now
                        if (base_v < 0) {
                            while (ld_acquire(&g_ready[b]) == 0) __nanosleep(32);
                            base_v = g_base[b][w];
                        }
                        const int c = base_v - 1 + f0 + M;
                        if (c < CC) {
                            const float inv = 1.0f / (float)len;
                            float4 m = make_float4(acc.x * inv, acc.y * inv,
                                                   acc.z * inv, acc.w * inv);
                            reinterpret_cast<float4*>(
                                means + ((size_t)b * CC + c) * DD)[t] = m;
                        }
                    }
                    M++; ps = j;
                    acc = make_float4(0.f, 0.f, 0.f, 0.f);
                }
            }
            f4add(acc, v);
        }
        b0 = n0; b1 = n1; b2 = n2; b3 = n3;
    }
    g_tail[b][w][t] = acc;              // tail piece (always nonempty)
    __syncthreads();                    // (A) all edge-piece stores done

    if (t == 0) {
        while (ld_acquire(&g_ready[b]) == 0) __nanosleep(32);
        s_base = g_base[b][w];
    }
    __syncthreads();                    // (B) base + scan data visible
    const int base = s_base;

    // deferred interior means (pieces m=1,2 are interior iff a later flush exists)
    if (M >= 2) {
        const int c = base + f0;        // base-1+f0+1
        if (c < CC) {
            const float inv = 1.0f / (float)l1;
            float4 m = make_float4(h0.x * inv, h0.y * inv, h0.z * inv, h0.w * inv);
            reinterpret_cast<float4*>(means + ((size_t)b * CC + c) * DD)[t] = m;
        }
    }
    if (M >= 3) {
        const int c = base + f0 + 1;    // base-1+f0+2
        if (c < CC) {
            const float inv = 1.0f / (float)l2;
            float4 m = make_float4(h1.x * inv, h1.y * inv, h1.z * inv, h1.w * inv);
            reinterpret_cast<float4*>(means + ((size_t)b * CC + c) * DD)[t] = m;
        }
    }

    // arrival bumps (t0 only); release makes this block's partials visible
    if (t == 0) {
        int fc0 = -1, fc1 = -1;
        const int POPC = __popc(lo) + __popc(hi);
        const int ct = base + POPC - 1;           // tail piece's chunk
        if (ct >= 0 && ct < CC) {
            const int4 mt = g_chunk[b][ct];
            const int tgt = chunk_target(mt.y, mt.z);
            if (atomic_add_acq_rel(&g_arrive[b][ct], 1) + 1 == tgt) fc0 = ct;
        }
        if (M >= 1) {                              // separate head piece exists
            const int ch = base - 1 + f0;
            if (ch >= 0 && ch < CC) {
                const int4 mt = g_chunk[b][ch];
                const int tgt = chunk_target(mt.y, mt.z);
                if (atomic_add_acq_rel(&g_arrive[b][ch], 1) + 1 == tgt) fc1 = ch;
            }
        }
        s_f0 = fc0; s_f1 = fc1;
    }
    __syncthreads();                    // (C)

    if (s_f0 >= 0) finalize_chunk(b, s_f0, t, means);
    if (s_f1 >= 0) finalize_chunk(b, s_f1, t, means);

    // self-cleaning for graph replay
    if (t == 0) {
        if (atomic_add_acq_rel(&g_done[b], 1) == NW - 1) {
            g_done[b]  = 0;
            g_ready[b] = 0;
        }
    }
}

extern "C" void kernel_launch(void* const* d_in, const int* in_sizes, int n_in,
                              void* d_out, int out_size) {
    const float* x = nullptr;
    const float* boundaries = nullptr;
    for (int i = 0; i < n_in; i++) {
        if (in_sizes[i] == BB * LL * DD) x = (const float*)d_in[i];
        else if (in_sizes[i] == BB * LL) boundaries = (const float*)d_in[i];
    }

    float* out = (float*)d_out;
    const int means_elems = BB * CC * DD;
    const int write_cnts = (out_size > means_elems) ? 1 : 0;

    chunk_win_kernel<<<BB + BB * NW, 256>>>(
        x, boundaries, out, out + means_elems, write_cnts);
}

// round 8
// speedup vs baseline: 1.1571x; 1.1571x over previous
#include <cuda_runtime.h>
#include <cuda_bf16.h>

#define BB 8
#define LL 4096
#define DD 1024
#define CC 128
#define SLICE 32
#define MAXSL (LL / SLICE + CC)   // 256 slices max per batch
#define NSLICES (BB * MAXSL)      // 2048 global slice slots
#define POOL 740                  // 148 SMs * 5 CTAs/SM (guaranteed by launch_bounds)

// Packed metadata
__device__ int4 g_slice[BB][MAXSL];   // {s, e, chunk_id, 0}; s==e => unused
__device__ int4 g_chunk[BB][CC];      // {cnt, first slice, n slices, 0}
__device__ int  g_arrive[BB][CC];     // per-chunk arrival counters (reset by scan)
__device__ int  g_ready[BB];          // per-batch metadata-ready flags (self-cleaning)
__device__ int  g_fin;                // pool completion counter (self-cleaning)

// Partial sums scratch (multi-slice chunks only): 8 MB
__device__ float4 g_part[BB][MAXSL][DD / 4];

// --- memory-model helpers ---
__device__ __forceinline__ int atomic_add_acq_rel(int* p, int v) {
    int old;
    asm volatile("atom.add.acq_rel.gpu.s32 %0, [%1], %2;"
                 : "=r"(old) : "l"(p), "r"(v) : "memory");
    return old;
}
__device__ __forceinline__ void st_release(int* p, int v) {
    asm volatile("st.release.gpu.s32 [%0], %1;" :: "l"(p), "r"(v) : "memory");
}
__device__ __forceinline__ int ld_acquire(const int* p) {
    int v;
    asm volatile("ld.acquire.gpu.s32 %0, [%1];" : "=r"(v) : "l"(p) : "memory");
    return v;
}

// ---------------------------------------------------------------------------
// One fused kernel. bids 0..7 = scan blocks; bids 8..747 = persistent pool.
// ---------------------------------------------------------------------------
__global__ void __launch_bounds__(256, 5) chunk_fused_kernel(
        const float* __restrict__ x,
        const float* __restrict__ boundaries,
        float* __restrict__ means,
        float* __restrict__ cnts_out,
        int write_cnts) {
    const int t    = threadIdx.x;       // 0..255
    const int lane = t & 31;
    const int wid  = t >> 5;            // 0..7

    if (blockIdx.x < BB) {
        // =================== SCAN BLOCK (one per batch) ====================
        const int b = blockIdx.x;
        const float* bp = boundaries + (size_t)b * LL;

        __shared__ int wsum[8], wexcl[8], pos[CC + 1], snb, csum[4], cexcl[4];
        __shared__ int snsl, elist[CC], s_ne;
        if (t == 0) s_ne = 0;

        // phase 1: flags (16 tokens/thread) + ordered compaction
        const int base = t * 16;
        unsigned flags = 0;
        {
            const float4* bp4 = reinterpret_cast<const float4*>(bp + base);
#pragma unroll
            for (int q = 0; q < 4; q++) {
                float4 v = bp4[q];
                if (v.x > 0.5f) flags |= 1u << (q * 4 + 0);
                if (v.y > 0.5f) flags |= 1u << (q * 4 + 1);
                if (v.z > 0.5f) flags |= 1u << (q * 4 + 2);
                if (v.w > 0.5f) flags |= 1u << (q * 4 + 3);
            }
        }
        const int cnt = __popc(flags);

        int incl = cnt;
#pragma unroll
        for (int d = 1; d < 32; d <<= 1) {
            int v = __shfl_up_sync(0xFFFFFFFFu, incl, d);
            if (lane >= d) incl += v;
        }
        if (lane == 31) wsum[wid] = incl;
        __syncthreads();

        if (t < 8) {
            int v = wsum[t];
            int iv = v;
#pragma unroll
            for (int d = 1; d < 8; d <<= 1) {
                int u = __shfl_up_sync(0x000000FFu, iv, d);
                if (t >= d) iv += u;
            }
            wexcl[t] = iv - v;
            if (t == 7) snb = iv;
        }
        __syncthreads();

        {
            int idx = wexcl[wid] + (incl - cnt);
            unsigned f = flags;
            while (f) {
                int i = __ffs(f) - 1;
                f &= f - 1;
                if (idx <= CC) pos[idx] = base + i;
                idx++;
            }
        }
        __syncthreads();

        const int nb = snb;
        const int valid = nb < CC ? nb : CC;

        // phase 2: chunk ranges + slice-count scan
        int s0 = 0, e0 = 0, len = 0, nsl = 0;
        if (t < CC && t < valid) {
            s0 = pos[t];
            e0 = (t + 1 < nb) ? pos[t + 1] : LL;
            len = e0 - s0;
            nsl = (len + SLICE - 1) / SLICE;
        }

        int cincl = nsl;
#pragma unroll
        for (int d = 1; d < 32; d <<= 1) {
            int v = __shfl_up_sync(0xFFFFFFFFu, cincl, d);
            if (lane >= d) cincl += v;
        }
        if (t < CC && lane == 31) csum[wid] = cincl;
        __syncthreads();

        if (t < 4) {
            int v = csum[t];
            int iv = v;
#pragma unroll
            for (int d = 1; d < 4; d <<= 1) {
                int u = __shfl_up_sync(0x0000000Fu, iv, d);
                if (t >= d) iv += u;
            }
            cexcl[t] = iv - v;
            if (t == 3) snsl = iv;
        }
        __syncthreads();

        const int nsl_total = snsl;

        if (t < CC) {
            const int soff = cexcl[wid] + (cincl - nsl);
            g_chunk[b][t]  = make_int4(len, soff, nsl, 0);
            g_arrive[b][t] = 0;
            if (len > 0) {
                int si = soff;
                for (int ss = s0; ss < e0; ss += SLICE, si++) {
                    int ee = ss + SLICE;
                    g_slice[b][si] = make_int4(ss, ee < e0 ? ee : e0, t, 0);
                }
            } else {
                elist[atomicAdd(&s_ne, 1)] = t;
            }
        }
        if (t >= nsl_total) g_slice[b][t] = make_int4(0, 0, 0, 0);
        __syncthreads();

        if (t == 0) st_release(&g_ready[b], 1);   // publish EARLY

        // post-release: zero empty-chunk means + cnts output
        const int ne = s_ne;
        {
            const float4 z = make_float4(0.f, 0.f, 0.f, 0.f);
            for (int i = 0; i < ne; i++) {
                reinterpret_cast<float4*>(
                    means + ((size_t)b * CC + elist[i]) * DD)[t] = z;
            }
        }
        if (write_cnts && t < CC) cnts_out[b * CC + t] = (float)g_chunk[b][t].x;
        return;
    }

    // ================== PERSISTENT POOL BLOCK ==================
    __shared__ int s_last;

    if (t == 0) {
#pragma unroll
        for (int b = 0; b < BB; b++) {
            while (ld_acquire(&g_ready[b]) == 0) __nanosleep(32);
        }
    }
    __syncthreads();                      // metadata of all batches visible

    for (int sg = (int)blockIdx.x - BB; sg < NSLICES; sg += POOL) {
        const int b  = sg >> 8;           // / MAXSL
        const int sl = sg & (MAXSL - 1);

        const int4 se = g_slice[b][sl];   // {s, e, chunk, 0}
        const int n = se.y - se.x;
        if (n == 0) continue;

        const float4* __restrict__ xp =
            reinterpret_cast<const float4*>(x + (size_t)b * LL * DD) +
            (size_t)se.x * (DD / 4) + t;

        float4 a0 = make_float4(0.f, 0.f, 0.f, 0.f);
        float4 a1 = make_float4(0.f, 0.f, 0.f, 0.f);
        float4 a2 = make_float4(0.f, 0.f, 0.f, 0.f);
        float4 a3 = make_float4(0.f, 0.f, 0.f, 0.f);

        if (n == SLICE) {
#pragma unroll
            for (int i = 0; i < SLICE; i += 4) {
                float4 v0 = xp[(size_t)(i + 0) * (DD / 4)];
                float4 v1 = xp[(size_t)(i + 1) * (DD / 4)];
                float4 v2 = xp[(size_t)(i + 2) * (DD / 4)];
                float4 v3 = xp[(size_t)(i + 3) * (DD / 4)];
                a0.x += v0.x; a0.y += v0.y; a0.z += v0.z; a0.w += v0.w;
                a1.x += v1.x; a1.y += v1.y; a1.z += v1.z; a1.w += v1.w;
                a2.x += v2.x; a2.y += v2.y; a2.z += v2.z; a2.w += v2.w;
                a3.x += v3.x; a3.y += v3.y; a3.z += v3.z; a3.w += v3.w;
            }
        } else {
            int i = 0;
#pragma unroll 4
            for (; i + 1 < n; i += 2) {
                float4 v0 = xp[(size_t)i * (DD / 4)];
                float4 v1 = xp[(size_t)(i + 1) * (DD / 4)];
                a0.x += v0.x; a0.y += v0.y; a0.z += v0.z; a0.w += v0.w;
                a1.x += v1.x; a1.y += v1.y; a1.z += v1.z; a1.w += v1.w;
            }
            if (i < n) {
                float4 v0 = xp[(size_t)i * (DD / 4)];
                a0.x += v0.x; a0.y += v0.y; a0.z += v0.z; a0.w += v0.w;
            }
        }

        a0.x += a2.x; a0.y += a2.y; a0.z += a2.z; a0.w += a2.w;
        a1.x += a3.x; a1.y += a3.y; a1.z += a3.z; a1.w += a3.w;
        a0.x += a1.x; a0.y += a1.y; a0.z += a1.z; a0.w += a1.w;

        const int c = se.z;
        const int4 meta = g_chunk[b][c];  // {cnt, first slice, nsl, 0}
        float4* __restrict__ mp =
            reinterpret_cast<float4*>(means + ((size_t)b * CC + c) * DD);

        if (meta.z == 1) {
            const float inv = 1.0f / (float)n;
            a0.x *= inv; a0.y *= inv; a0.z *= inv; a0.w *= inv;
            mp[t] = a0;
        } else {
            g_part[b][sl][t] = a0;
            __syncthreads();              // all partial stores before t0's release
            if (t == 0) {
                s_last = (atomic_add_acq_rel(&g_arrive[b][c], 1) == meta.z - 1);
            }
            __syncthreads();              // distribute acquire
            if (s_last) {
                float4 acc = make_float4(0.f, 0.f, 0.f, 0.f);
                for (int i = 0; i < meta.z; i++) {   // fixed order: deterministic
                    float4 v = g_part[b][meta.y + i][t];
                    acc.x += v.x; acc.y += v.y; acc.z += v.z; acc.w += v.w;
                }
                const float inv = 1.0f / (float)meta.x;
                acc.x *= inv; acc.y *= inv; acc.z *= inv; acc.w *= inv;
                mp[t] = acc;
            }
        }
    }

    // self-cleaning for graph replay: last pool block resets the flags
    if (t == 0) {
        if (atomic_add_acq_rel(&g_fin, 1) == POOL - 1) {
#pragma unroll
            for (int b = 0; b < BB; b++) g_ready[b] = 0;
            g_fin = 0;
        }
    }
}

extern "C" void kernel_launch(void* const* d_in, const int* in_sizes, int n_in,
                              void* d_out, int out_size) {
    const float* x = nullptr;
    const float* boundaries = nullptr;
    for (int i = 0; i < n_in; i++) {
        if (in_sizes[i] == BB * LL * DD) x = (const float*)d_in[i];
        else if (in_sizes[i] == BB * LL) boundaries = (const float*)d_in[i];
    }

    float* out = (float*)d_out;
    const int means_elems = BB * CC * DD;
    const int write_cnts = (out_size > means_elems) ? 1 : 0;

    chunk_fused_kernel<<<BB + POOL, 256>>>(
        x, boundaries, out, out + means_elems, write_cnts);
}

// round 9
// speedup vs baseline: 1.2235x; 1.0574x over previous
#include <cuda_runtime.h>
#include <cuda_bf16.h>

#define BB 8
#define LL 4096
#define DD 1024
#define CC 128
#define WIN 64
#define NW (LL / WIN)            // 64 windows per batch
#define NWTOT (BB * NW)          // 512 window blocks

// Scan-published metadata
__device__ int4 g_chunk[BB][CC];      // {cnt, s, e, 0}
__device__ int  g_arrive[BB][CC];     // per-chunk arrival counters (reset by scan)
__device__ int  g_ready[BB];          // per-batch ready flags (self-cleaning)
__device__ int  g_fin;                // window completion counter (self-cleaning)

// Window edge pieces (window-indexed: no scan dependency to store)
__device__ float4 g_head[BB][NW][DD / 4];   // 4 MB
__device__ float4 g_tail[BB][NW][DD / 4];   // 4 MB

// --- memory-model helpers ---
__device__ __forceinline__ int atomic_add_acq_rel(int* p, int v) {
    int old;
    asm volatile("atom.add.acq_rel.gpu.s32 %0, [%1], %2;"
                 : "=r"(old) : "l"(p), "r"(v) : "memory");
    return old;
}
__device__ __forceinline__ void st_release(int* p, int v) {
    asm volatile("st.release.gpu.s32 [%0], %1;" :: "l"(p), "r"(v) : "memory");
}
__device__ __forceinline__ int ld_acquire(const int* p) {
    int v;
    asm volatile("ld.acquire.gpu.s32 %0, [%1];" : "=r"(v) : "l"(p) : "memory");
    return v;
}
__device__ __forceinline__ void f4add(float4& a, const float4& v) {
    a.x += v.x; a.y += v.y; a.z += v.z; a.w += v.w;
}

// sum of tokens [s, e) of this window for column t; xp = col-t base, stride 256
__device__ __forceinline__ float4 sum_range(const float4* __restrict__ xp,
                                            int s, int e) {
    float4 a0 = make_float4(0.f, 0.f, 0.f, 0.f);
    float4 a1 = a0, a2 = a0, a3 = a0;
    if (s == 0 && e == WIN) {
#pragma unroll
        for (int i = 0; i < WIN; i += 4) {
            float4 v0 = xp[(size_t)(i + 0) * 256];
            float4 v1 = xp[(size_t)(i + 1) * 256];
            float4 v2 = xp[(size_t)(i + 2) * 256];
            float4 v3 = xp[(size_t)(i + 3) * 256];
            f4add(a0, v0); f4add(a1, v1); f4add(a2, v2); f4add(a3, v3);
        }
    } else {
        int i = s;
#pragma unroll 4
        for (; i + 1 < e; i += 2) {
            float4 v0 = xp[(size_t)i * 256];
            float4 v1 = xp[(size_t)(i + 1) * 256];
            f4add(a0, v0); f4add(a1, v1);
        }
        if (i < e) { float4 v0 = xp[(size_t)i * 256]; f4add(a0, v0); }
    }
    f4add(a0, a2); f4add(a1, a3); f4add(a0, a1);
    return a0;
}

// number of window blocks contributing edge pieces to chunk [s, e)
__device__ __forceinline__ int chunk_target(int s, int e) {
    const int w0 = s >> 6, w1 = (e - 1) >> 6;
    if (w1 > w0) return w1 - w0 + 1;
    return (((s & 63) == 0) || ((e & 63) == 0)) ? 1 : 0;
}

// deterministic finalize over fixed window order
__device__ __forceinline__ void finalize_chunk(int b, int c, int t,
                                               float* __restrict__ means) {
    const int4 mt = g_chunk[b][c];       // {cnt, s, e, 0}
    const int w0 = mt.y >> 6, w1 = (mt.z - 1) >> 6;
    float4 a = make_float4(0.f, 0.f, 0.f, 0.f);
    for (int ww = w0; ww <= w1; ww++) {
        float4 v = (((ww + 1) << 6) <= mt.z) ? g_tail[b][ww][t]
                                             : g_head[b][ww][t];
        f4add(a, v);
    }
    const float inv = 1.0f / (float)mt.x;
    a.x *= inv; a.y *= inv; a.z *= inv; a.w *= inv;
    reinterpret_cast<float4*>(means + ((size_t)b * CC + c) * DD)[t] = a;
}

// ---------------------------------------------------------------------------
// One kernel. bids 0..7 = scan blocks; bids 8..519 = window blocks.
// ---------------------------------------------------------------------------
__global__ void __launch_bounds__(256, 4) chunk_win_kernel(
        const float* __restrict__ x,
        const float* __restrict__ boundaries,
        float* __restrict__ means,
        float* __restrict__ cnts_out,
        int write_cnts) {
    const int t    = threadIdx.x;
    const int lane = t & 31;
    const int wid  = t >> 5;

    if (blockIdx.x < BB) {
        // ====================== SCAN BLOCK ======================
        const int b = blockIdx.x;
        __shared__ int wsum[8], wexcl[8], pos[CC + 1], snb, elist[CC], s_ne;
        if (t == 0) s_ne = 0;

        const float* bp = boundaries + (size_t)b * LL;
        const int base16 = t * 16;
        unsigned flags = 0;
        {
            const float4* bp4 = reinterpret_cast<const float4*>(bp + base16);
#pragma unroll
            for (int q = 0; q < 4; q++) {
                float4 v = bp4[q];
                if (v.x > 0.5f) flags |= 1u << (q * 4 + 0);
                if (v.y > 0.5f) flags |= 1u << (q * 4 + 1);
                if (v.z > 0.5f) flags |= 1u << (q * 4 + 2);
                if (v.w > 0.5f) flags |= 1u << (q * 4 + 3);
            }
        }
        const int cnt = __popc(flags);

        int incl = cnt;
#pragma unroll
        for (int d = 1; d < 32; d <<= 1) {
            int v = __shfl_up_sync(0xFFFFFFFFu, incl, d);
            if (lane >= d) incl += v;
        }
        if (lane == 31) wsum[wid] = incl;
        __syncthreads();

        if (t < 8) {
            int v = wsum[t];
            int iv = v;
#pragma unroll
            for (int d = 1; d < 8; d <<= 1) {
                int u = __shfl_up_sync(0x000000FFu, iv, d);
                if (t >= d) iv += u;
            }
            wexcl[t] = iv - v;
            if (t == 7) snb = iv;
        }
        __syncthreads();

        {
            int idx = wexcl[wid] + (incl - cnt);
            unsigned f = flags;
            while (f) {
                int i = __ffs(f) - 1;
                f &= f - 1;
                if (idx <= CC) pos[idx] = base16 + i;
                idx++;
            }
        }
        __syncthreads();

        const int nb = snb;
        const int valid = nb < CC ? nb : CC;

        if (t < CC) {
            int len = 0, s0 = 0, e0 = 0;
            if (t < valid) {
                s0 = pos[t];
                e0 = (t + 1 < nb) ? pos[t + 1] : LL;
                len = e0 - s0;
            }
            g_chunk[b][t]  = make_int4(len, s0, e0, 0);
            g_arrive[b][t] = 0;
            if (len == 0) elist[atomicAdd(&s_ne, 1)] = t;
        }
        __syncthreads();

        if (t == 0) st_release(&g_ready[b], 1);   // publish EARLY

        // post-release housekeeping
        const int ne = s_ne;
        const float4 z = make_float4(0.f, 0.f, 0.f, 0.f);
        for (int i = 0; i < ne; i++) {
            reinterpret_cast<float4*>(
                means + ((size_t)b * CC + elist[i]) * DD)[t] = z;
        }
        if (write_cnts && t < CC) cnts_out[b * CC + t] = (float)g_chunk[b][t].x;
        return;
    }

    // ====================== WINDOW BLOCK ======================
    const int gw = blockIdx.x - BB;
    const int b  = gw >> 6;             // / NW
    const int w  = gw & (NW - 1);

    __shared__ int s_red[8];
    __shared__ int s_base, s_c0, s_c1;

    // 1. window boundary mask (identical in every warp; no scan dependency)
    const float* bpt = boundaries + (size_t)b * LL + w * WIN;
    const unsigned lo = __ballot_sync(0xFFFFFFFFu, bpt[lane]      > 0.5f);
    const unsigned hi = __ballot_sync(0xFFFFFFFFu, bpt[32 + lane] > 0.5f);
    const unsigned long long m  = ((unsigned long long)hi << 32) | lo;
    const int f0 = (int)(m & 1ull);
    const unsigned long long mi = m & ~1ull;    // in-window splits (j > 0)

    // 2. base = #boundaries before this window (cheap L2 reduction; <=16KB)
    {
        int cb = 0;
        const int nb4 = w * (WIN / 4);          // float4 count to scan
        const float4* bb4 =
            reinterpret_cast<const float4*>(boundaries + (size_t)b * LL);
        for (int i = t; i < nb4; i += 256) {
            float4 v = bb4[i];
            cb += (v.x > 0.5f) + (v.y > 0.5f) + (v.z > 0.5f) + (v.w > 0.5f);
        }
#pragma unroll
        for (int d = 16; d > 0; d >>= 1) cb += __shfl_xor_sync(0xFFFFFFFFu, cb, d);
        if (lane == 0) s_red[wid] = cb;
        __syncthreads();
        if (t == 0) {
            int s = 0;
#pragma unroll
            for (int i = 0; i < 8; i++) s += s_red[i];
            s_base = s;
        }
        __syncthreads();
    }
    const int base = s_base;

    // 3. stream pieces (boundaries precomputed -> clean load loops)
    const float4* __restrict__ xp =
        reinterpret_cast<const float4*>(x) +
        (size_t)(b * LL + w * WIN) * (DD / 4) + t;

    {
        unsigned long long rem = mi;
        int ps = 0, pidx = 0;
        for (;;) {
            const int pe = rem ? (__ffsll(rem) - 1) : WIN;
            float4 a = sum_range(xp, ps, pe);
            if (pe == WIN) {
                g_tail[b][w][t] = a;            // last piece always -> tail
                break;
            }
            if (pidx == 0) {
                g_head[b][w][t] = a;            // head piece
            } else {
                // interior piece = complete chunk; finalize immediately
                const int c = base - 1 + f0 + pidx;
                if (c < CC) {
                    const float inv = 1.0f / (float)(pe - ps);
                    float4 mm = make_float4(a.x * inv, a.y * inv,
                                            a.z * inv, a.w * inv);
                    reinterpret_cast<float4*>(
                        means + ((size_t)b * CC + c) * DD)[t] = mm;
                }
            }
            ps = pe;
            rem &= rem - 1;
            pidx++;
        }
    }
    __syncthreads();                            // edge stores complete

    // 4. epilogue: arrival bumps + unique deterministic finalize
    if (t == 0) {
        while (ld_acquire(&g_ready[b]) == 0) __nanosleep(32);
        int c0 = -1, c1 = -1;
        const int ct = base + __popcll(m) - 1;          // tail piece's chunk
        if (ct >= 0 && ct < CC) {
            const int4 mt = g_chunk[b][ct];
            if (atomic_add_acq_rel(&g_arrive[b][ct], 1) + 1 ==
                chunk_target(mt.y, mt.z)) c0 = ct;
        }
        if (mi != 0ull) {                               // separate head piece
            const int ch = base - 1 + f0;
            if (ch >= 0 && ch < CC) {
                const int4 mt = g_chunk[b][ch];
                if (atomic_add_acq_rel(&g_arrive[b][ch], 1) + 1 ==
                    chunk_target(mt.y, mt.z)) c1 = ch;
            }
        }
        s_c0 = c0; s_c1 = c1;
    }
    __syncthreads();

    if (s_c0 >= 0) finalize_chunk(b, s_c0, t, means);
    if (s_c1 >= 0) finalize_chunk(b, s_c1, t, means);

    // self-cleaning for graph replay
    if (t == 0) {
        if (atomic_add_acq_rel(&g_fin, 1) == NWTOT - 1) {
#pragma unroll
            for (int i = 0; i < BB; i++) g_ready[i] = 0;
            g_fin = 0;
        }
    }
}

extern "C" void kernel_launch(void* const* d_in, const int* in_sizes, int n_in,
                              void* d_out, int out_size) {
    const float* x = nullptr;
    const float* boundaries = nullptr;
    for (int i = 0; i < n_in; i++) {
        if (in_sizes[i] == BB * LL * DD) x = (const float*)d_in[i];
        else if (in_sizes[i] == BB * LL) boundaries = (const float*)d_in[i];
    }

    float* out = (float*)d_out;
    const int means_elems = BB * CC * DD;
    const int write_cnts = (out_size > means_elems) ? 1 : 0;

    chunk_win_kernel<<<BB + NWTOT, 256>>>(
        x, boundaries, out, out + means_elems, write_cnts);
}

// round 10
// speedup vs baseline: 1.2932x; 1.0570x over previous
#include <cuda_runtime.h>
#include <cuda_bf16.h>

#define BB 8
#define LL 4096
#define DD 1024
#define CC 128
#define SLICE 32
#define MAXSL (LL / SLICE + CC)   // 256 slices max per batch

// Packed metadata
__device__ int4 g_slice[BB][MAXSL];   // {s, e, chunk_id, 0}; s==e => unused
__device__ int4 g_chunk[BB][CC];      // {cnt, first slice, n slices, 0}
__device__ int  g_arrive[BB][CC];     // per-chunk arrival counters (reset by scan)
__device__ int  g_ready[BB];          // per-batch metadata-ready flags (self-cleaning)
__device__ int  g_done[BB];           // per-batch pool-block completion counters

// Partial sums scratch (multi-slice chunks only): 8 MB
__device__ float4 g_part[BB][MAXSL][DD / 4];

// --- memory-model helpers ---
__device__ __forceinline__ int atomic_add_acq_rel(int* p, int v) {
    int old;
    asm volatile("atom.add.acq_rel.gpu.s32 %0, [%1], %2;"
                 : "=r"(old) : "l"(p), "r"(v) : "memory");
    return old;
}
__device__ __forceinline__ void st_release(int* p, int v) {
    asm volatile("st.release.gpu.s32 [%0], %1;" :: "l"(p), "r"(v) : "memory");
}
__device__ __forceinline__ int ld_acquire(const int* p) {
    int v;
    asm volatile("ld.acquire.gpu.s32 %0, [%1];" : "=r"(v) : "l"(p) : "memory");
    return v;
}

// Cold path: deterministic fixed-order reduction of a chunk's slice partials.
// __noinline__ keeps its registers out of the hot streaming path.
__device__ __noinline__ void finalize_multi(int b, int c, int t,
                                            int first_sl, int nsl, int cnt,
                                            float4* __restrict__ mp) {
    float4 acc = make_float4(0.f, 0.f, 0.f, 0.f);
    for (int i = 0; i < nsl; i++) {
        float4 v = g_part[b][first_sl + i][t];
        acc.x += v.x; acc.y += v.y; acc.z += v.z; acc.w += v.w;
    }
    const float inv = 1.0f / (float)cnt;
    acc.x *= inv; acc.y *= inv; acc.z *= inv; acc.w *= inv;
    mp[t] = acc;
}

// ---------------------------------------------------------------------------
// One fused kernel, 8 + BB*MAXSL blocks, 256 threads each.
//   bid 0..7      : per-batch boundary scan -> metadata; release ready flag.
//   bid 8..2055   : pool blocks; acquire-spin on ready flag, then pool+finalize.
// __launch_bounds__(256, 8) caps regs at 32 -> 8 CTAs/SM residency.
// ---------------------------------------------------------------------------
__global__ void __launch_bounds__(256, 8) chunk_fused_kernel(
        const float* __restrict__ x,
        const float* __restrict__ boundaries,
        float* __restrict__ means,
        float* __restrict__ cnts_out,
        int write_cnts) {
    const int t    = threadIdx.x;       // 0..255
    const int lane = t & 31;
    const int wid  = t >> 5;            // 0..7

    if (blockIdx.x < BB) {
        // =================== SCAN BLOCK (one per batch) ====================
        const int b = blockIdx.x;
        const float* bp = boundaries + (size_t)b * LL;

        __shared__ int wsum[8], wexcl[8], pos[CC + 1], snb, csum[4], cexcl[4];
        __shared__ int snsl, elist[CC], s_ne;
        if (t == 0) s_ne = 0;

        // phase 1: flags (16 tokens/thread) + ordered compaction
        const int base = t * 16;
        unsigned flags = 0;
        {
            const float4* bp4 = reinterpret_cast<const float4*>(bp + base);
#pragma unroll
            for (int q = 0; q < 4; q++) {
                float4 v = bp4[q];
                if (v.x > 0.5f) flags |= 1u << (q * 4 + 0);
                if (v.y > 0.5f) flags |= 1u << (q * 4 + 1);
                if (v.z > 0.5f) flags |= 1u << (q * 4 + 2);
                if (v.w > 0.5f) flags |= 1u << (q * 4 + 3);
            }
        }
        const int cnt = __popc(flags);

        int incl = cnt;
#pragma unroll
        for (int d = 1; d < 32; d <<= 1) {
            int v = __shfl_up_sync(0xFFFFFFFFu, incl, d);
            if (lane >= d) incl += v;
        }
        if (lane == 31) wsum[wid] = incl;
        __syncthreads();

        if (t < 8) {
            int v = wsum[t];
            int iv = v;
#pragma unroll
            for (int d = 1; d < 8; d <<= 1) {
                int u = __shfl_up_sync(0x000000FFu, iv, d);
                if (t >= d) iv += u;
            }
            wexcl[t] = iv - v;
            if (t == 7) snb = iv;
        }
        __syncthreads();

        {
            int idx = wexcl[wid] + (incl - cnt);
            unsigned f = flags;
            while (f) {
                int i = __ffs(f) - 1;
                f &= f - 1;
                if (idx <= CC) pos[idx] = base + i;
                idx++;
            }
        }
        __syncthreads();

        const int nb = snb;
        const int valid = nb < CC ? nb : CC;

        // phase 2: chunk ranges + slice-count scan
        int s0 = 0, e0 = 0, len = 0, nsl = 0;
        if (t < CC && t < valid) {
            s0 = pos[t];
            e0 = (t + 1 < nb) ? pos[t + 1] : LL;
            len = e0 - s0;
            nsl = (len + SLICE - 1) / SLICE;
        }

        int cincl = nsl;
#pragma unroll
        for (int d = 1; d < 32; d <<= 1) {
            int v = __shfl_up_sync(0xFFFFFFFFu, cincl, d);
            if (lane >= d) cincl += v;
        }
        if (t < CC && lane == 31) csum[wid] = cincl;
        __syncthreads();

        if (t < 4) {
            int v = csum[t];
            int iv = v;
#pragma unroll
            for (int d = 1; d < 4; d <<= 1) {
                int u = __shfl_up_sync(0x0000000Fu, iv, d);
                if (t >= d) iv += u;
            }
            cexcl[t] = iv - v;
            if (t == 3) snsl = iv;
        }
        __syncthreads();

        const int nsl_total = snsl;

        if (t < CC) {
            const int soff = cexcl[wid] + (cincl - nsl);
            g_chunk[b][t]  = make_int4(len, soff, nsl, 0);
            g_arrive[b][t] = 0;
            if (len > 0) {
                int si = soff;
                for (int ss = s0; ss < e0; ss += SLICE, si++) {
                    int ee = ss + SLICE;
                    g_slice[b][si] = make_int4(ss, ee < e0 ? ee : e0, t, 0);
                }
            } else {
                elist[atomicAdd(&s_ne, 1)] = t;
            }
        }
        if (t >= nsl_total) g_slice[b][t] = make_int4(0, 0, 0, 0);
        __syncthreads();

        if (t == 0) st_release(&g_ready[b], 1);   // publish EARLY

        // post-release: zero empty-chunk means + cnts output
        const int ne = s_ne;
        {
            const float4 z = make_float4(0.f, 0.f, 0.f, 0.f);
            for (int i = 0; i < ne; i++) {
                reinterpret_cast<float4*>(
                    means + ((size_t)b * CC + elist[i]) * DD)[t] = z;
            }
        }
        if (write_cnts && t < CC) cnts_out[b * CC + t] = (float)g_chunk[b][t].x;
        return;
    }

    // ======================= POOL BLOCK =======================
    const int idx = blockIdx.x - BB;
    const int b   = idx >> 8;            // / MAXSL
    const int sl  = idx & (MAXSL - 1);

    __shared__ int s_last;

    if (t == 0) {
        while (ld_acquire(&g_ready[b]) == 0) __nanosleep(64);
    }
    __syncthreads();                      // distribute acquire to all threads

    const int4 se = g_slice[b][sl];       // {s, e, chunk, 0}
    const int n = se.y - se.x;

    if (n > 0) {
        // 32-bit offset math (fits: 8*4096*1024 < 2^31) to save registers
        const float4* __restrict__ xp =
            reinterpret_cast<const float4*>(x) +
            (b * LL + se.x) * (DD / 4) + t;

        float4 a0 = make_float4(0.f, 0.f, 0.f, 0.f);
        float4 a1 = make_float4(0.f, 0.f, 0.f, 0.f);

        if (n == SLICE) {
            // full unroll, 2 accumulators: ptxas batches loads to the 32-reg budget
#pragma unroll
            for (int i = 0; i < SLICE; i += 2) {
                float4 v0 = xp[(i + 0) * (DD / 4)];
                float4 v1 = xp[(i + 1) * (DD / 4)];
                a0.x += v0.x; a0.y += v0.y; a0.z += v0.z; a0.w += v0.w;
                a1.x += v1.x; a1.y += v1.y; a1.z += v1.z; a1.w += v1.w;
            }
        } else {
            int i = 0;
#pragma unroll 4
            for (; i + 1 < n; i += 2) {
                float4 v0 = xp[(i + 0) * (DD / 4)];
                float4 v1 = xp[(i + 1) * (DD / 4)];
                a0.x += v0.x; a0.y += v0.y; a0.z += v0.z; a0.w += v0.w;
                a1.x += v1.x; a1.y += v1.y; a1.z += v1.z; a1.w += v1.w;
            }
            if (i < n) {
                float4 v0 = xp[i * (DD / 4)];
                a0.x += v0.x; a0.y += v0.y; a0.z += v0.z; a0.w += v0.w;
            }
        }
        a0.x += a1.x; a0.y += a1.y; a0.z += a1.z; a0.w += a1.w;

        const int c = se.z;
        const int4 meta = g_chunk[b][c];  // {cnt, first slice, nsl, 0}
        float4* __restrict__ mp =
            reinterpret_cast<float4*>(means + ((size_t)b * CC + c) * DD);

        if (meta.z == 1) {
            const float inv = 1.0f / (float)n;
            a0.x *= inv; a0.y *= inv; a0.z *= inv; a0.w *= inv;
            mp[t] = a0;
        } else {
            // publish partial; one release-atomic per block (no per-thread fences)
            g_part[b][sl][t] = a0;
            __syncthreads();              // all partial stores before t0's release
            if (t == 0) {
                s_last = (atomic_add_acq_rel(&g_arrive[b][c], 1) == meta.z - 1);
            }
            __syncthreads();              // distribute acquire
            if (s_last) {
                finalize_multi(b, c, t, meta.y, meta.z, meta.x, mp);
            }
        }
    }

    // self-cleaning for graph replay: last pool block of the batch resets flags
    if (t == 0) {
        int old = atomic_add_acq_rel(&g_done[b], 1);
        if (old == MAXSL - 1) {
            g_ready[b] = 0;
            g_done[b]  = 0;
        }
    }
}

extern "C" void kernel_launch(void* const* d_in, const int* in_sizes, int n_in,
                              void* d_out, int out_size) {
    const float* x = nullptr;
    const float* boundaries = nullptr;
    for (int i = 0; i < n_in; i++) {
        if (in_sizes[i] == BB * LL * DD) x = (const float*)d_in[i];
        else if (in_sizes[i] == BB * LL) boundaries = (const float*)d_in[i];
    }

    float* out = (float*)d_out;
    const int means_elems = BB * CC * DD;
    const int write_cnts = (out_size > means_elems) ? 1 : 0;

    chunk_fused_kernel<<<BB + BB * MAXSL, 256>>>(
        x, boundaries, out, out + means_elems, write_cnts);
}